// round 8
// baseline (speedup 1.0000x reference)
#include <cuda_runtime.h>
#include <cstdint>

#define N_NODES 50000
#define HIDDEN  64
#define INDIM   512
#define OUTDIM  40

// Scratch (device globals)
__device__ __align__(16) float g_hs[N_NODES * HIDDEN];    // dinv[i] * h[i]
__device__ __align__(16) float g_agg[N_NODES * HIDDEN];   // aggregated messages
__device__ __align__(16) float g_deg[N_NODES];
__device__ __align__(16) float g_dinv[N_NODES];

// ---------------------------------------------------------------------------
// Degree: deg[i] = 1 (self loop) + #edges with dst==i
// ---------------------------------------------------------------------------
__global__ void init_deg_kernel(int n) {
    int i = blockIdx.x * blockDim.x + threadIdx.x;
    if (i < n) g_deg[i] = 1.0f;
}

__global__ void deg_accum_kernel(const int* __restrict__ dst, int E, int n) {
    int e = blockIdx.x * blockDim.x + threadIdx.x;
    if (e < E) {
        int d = dst[e];
        if ((unsigned)d < (unsigned)n) atomicAdd(&g_deg[d], 1.0f);
    }
}

// ---------------------------------------------------------------------------
// GEMM1 (tensor cores, tf32): h[n,64] = X[n,512] @ W1[512,64]
// Fused epilogue: d = rsqrt(deg[row]); hs = d*h; agg = d*hs; dinv[row] = d.
// ---------------------------------------------------------------------------
__device__ __forceinline__ uint32_t f2tf32(float f) {
    uint32_t r;
    asm("cvt.rna.tf32.f32 %0, %1;" : "=r"(r) : "f"(f));
    return r;
}

#define XS_STRIDE 36
#define WS_STRIDE 72

__global__ __launch_bounds__(256) void gemm1_mma_kernel(
    const float* __restrict__ X, const float* __restrict__ W, int n)
{
    __shared__ uint32_t Xs[128 * XS_STRIDE];
    __shared__ uint32_t Ws[32 * WS_STRIDE];

    const int tid  = threadIdx.x;
    const int lane = tid & 31;
    const int wid  = tid >> 5;
    const int gid  = lane >> 2;
    const int tig  = lane & 3;
    const int wrow = wid * 16;
    const int row0 = blockIdx.x * 128;

    float acc[8][4] = {};

    for (int k0 = 0; k0 < INDIM; k0 += 32) {
        #pragma unroll
        for (int t = 0; t < 4; t++) {
            int s = t * 256 + tid;
            int r = s >> 3, q = s & 7;
            int rr = row0 + r; if (rr >= n) rr = n - 1;
            float4 v = *(const float4*)(X + (size_t)rr * INDIM + k0 + q * 4);
            uint4 u = make_uint4(f2tf32(v.x), f2tf32(v.y), f2tf32(v.z), f2tf32(v.w));
            *(uint4*)(Xs + r * XS_STRIDE + q * 4) = u;
        }
        #pragma unroll
        for (int t = 0; t < 2; t++) {
            int s = t * 256 + tid;
            int kk = s >> 4, q = s & 15;
            float4 v = *(const float4*)(W + (size_t)(k0 + kk) * HIDDEN + q * 4);
            uint4 u = make_uint4(f2tf32(v.x), f2tf32(v.y), f2tf32(v.z), f2tf32(v.w));
            *(uint4*)(Ws + kk * WS_STRIDE + q * 4) = u;
        }
        __syncthreads();

        #pragma unroll
        for (int kk = 0; kk < 32; kk += 8) {
            uint32_t a0 = Xs[(wrow + gid) * XS_STRIDE + kk + tig];
            uint32_t a1 = Xs[(wrow + gid + 8) * XS_STRIDE + kk + tig];
            uint32_t a2 = Xs[(wrow + gid) * XS_STRIDE + kk + tig + 4];
            uint32_t a3 = Xs[(wrow + gid + 8) * XS_STRIDE + kk + tig + 4];
            #pragma unroll
            for (int nb = 0; nb < 8; nb++) {
                uint32_t b0 = Ws[(kk + tig) * WS_STRIDE + nb * 8 + gid];
                uint32_t b1 = Ws[(kk + tig + 4) * WS_STRIDE + nb * 8 + gid];
                asm volatile(
                    "mma.sync.aligned.m16n8k8.row.col.f32.tf32.tf32.f32 "
                    "{%0,%1,%2,%3}, {%4,%5,%6,%7}, {%8,%9}, {%0,%1,%2,%3};"
                    : "+f"(acc[nb][0]), "+f"(acc[nb][1]),
                      "+f"(acc[nb][2]), "+f"(acc[nb][3])
                    : "r"(a0), "r"(a1), "r"(a2), "r"(a3), "r"(b0), "r"(b1));
            }
        }
        __syncthreads();
    }

    // Fused epilogue
    const int rA = row0 + wrow + gid;
    const int rB = rA + 8;
    float dA = (rA < n) ? rsqrtf(g_deg[rA]) : 0.f;
    float dB = (rB < n) ? rsqrtf(g_deg[rB]) : 0.f;
    if (tig == 0) {
        if (rA < n) g_dinv[rA] = dA;
        if (rB < n) g_dinv[rB] = dB;
    }
    #pragma unroll
    for (int nb = 0; nb < 8; nb++) {
        int col = nb * 8 + 2 * tig;
        if (rA < n) {
            float h0 = dA * acc[nb][0], h1 = dA * acc[nb][1];
            *(float2*)(g_hs  + (size_t)rA * HIDDEN + col) = make_float2(h0, h1);
            *(float2*)(g_agg + (size_t)rA * HIDDEN + col) =
                make_float2(dA * h0, dA * h1);
        }
        if (rB < n) {
            float h2 = dB * acc[nb][2], h3 = dB * acc[nb][3];
            *(float2*)(g_hs  + (size_t)rB * HIDDEN + col) = make_float2(h2, h3);
            *(float2*)(g_agg + (size_t)rB * HIDDEN + col) =
                make_float2(dB * h2, dB * h3);
        }
    }
}

// ---------------------------------------------------------------------------
// Edge scatter: agg[dst,:] += dinv[dst] * hs[src,:]
// 16 threads per edge; leader lanes load indices/coef, broadcast via shfl.
// ---------------------------------------------------------------------------
__device__ __forceinline__ void red_add_v4(float* addr, float4 v) {
    asm volatile("red.global.add.v4.f32 [%0], {%1, %2, %3, %4};"
                 :: "l"(__cvta_generic_to_global(addr)),
                    "f"(v.x), "f"(v.y), "f"(v.z), "f"(v.w)
                 : "memory");
}

__global__ __launch_bounds__(256) void scatter_kernel(
    const int* __restrict__ src, const int* __restrict__ dst, int E, int n)
{
    int idx = blockIdx.x * blockDim.x + threadIdx.x;
    int e = idx >> 4, q = idx & 15;
    int lane = threadIdx.x & 31;
    int leader = lane & 16;   // lane 0 or 16 owns this edge's metadata

    int s_l = 0, d_l = 0;
    float c_l = 0.f;
    if ((lane & 15) == 0 && e < E) {
        s_l = src[e];
        d_l = dst[e];
        if ((unsigned)d_l < (unsigned)n) c_l = g_dinv[d_l];
    }
    int   s    = __shfl_sync(0xffffffffu, s_l, leader);
    int   d    = __shfl_sync(0xffffffffu, d_l, leader);
    float coef = __shfl_sync(0xffffffffu, c_l, leader);

    if (e >= E) return;
    if ((unsigned)s >= (unsigned)n || (unsigned)d >= (unsigned)n) return;

    float4 v = __ldg((const float4*)g_hs + s * 16 + q);
    v.x *= coef; v.y *= coef; v.z *= coef; v.w *= coef;
    red_add_v4(g_agg + (size_t)d * HIDDEN + q * 4, v);
}

// ---------------------------------------------------------------------------
// GEMM2: out[n,40] = relu(agg + b1) @ Wfc^T + bfc
// ---------------------------------------------------------------------------
__global__ __launch_bounds__(240) void gemm2_kernel(
    const float* __restrict__ b1, const float* __restrict__ Wfc,
    const float* __restrict__ bfc, float* __restrict__ out, int n)
{
    __shared__ float hs[24 * 68];
    __shared__ float Wt[64 * 40];
    __shared__ float bfs[40];

    const int tx = threadIdx.x;     // 0..9
    const int ty = threadIdx.y;     // 0..23
    const int tid = ty * 10 + tx;

    for (int idx = tid; idx < 64 * 40; idx += 240) {
        int o = idx % 40, j = idx / 40;
        Wt[j * 40 + o] = Wfc[o * 64 + j];
    }
    if (tid < 40) bfs[tid] = bfc[tid];

    const int row0 = blockIdx.x * 24;
    for (int idx = tid; idx < 24 * 16; idx += 240) {
        int r = idx >> 4, q = idx & 15;
        int grow = row0 + r;
        float4 v = make_float4(0.f, 0.f, 0.f, 0.f);
        if (grow < n) {
            v = ((const float4*)g_agg)[grow * 16 + q];
            float4 bb = ((const float4*)b1)[q];
            v.x = fmaxf(v.x + bb.x, 0.f);
            v.y = fmaxf(v.y + bb.y, 0.f);
            v.z = fmaxf(v.z + bb.z, 0.f);
            v.w = fmaxf(v.w + bb.w, 0.f);
        }
        *(float4*)(hs + r * 68 + q * 4) = v;
    }
    __syncthreads();

    float4 acc = make_float4(0.f, 0.f, 0.f, 0.f);
    #pragma unroll
    for (int j = 0; j < 64; j++) {
        float h = hs[ty * 68 + j];
        float4 w = *(const float4*)(Wt + j * 40 + tx * 4);
        acc.x += h * w.x;
        acc.y += h * w.y;
        acc.z += h * w.z;
        acc.w += h * w.w;
    }

    int grow = row0 + ty;
    if (grow < n) {
        float4 bb = *(const float4*)(bfs + tx * 4);
        acc.x += bb.x; acc.y += bb.y; acc.z += bb.z; acc.w += bb.w;
        *(float4*)(out + (size_t)grow * OUTDIM + tx * 4) = acc;
    }
}

// ---------------------------------------------------------------------------
extern "C" void kernel_launch(void* const* d_in, const int* in_sizes, int n_in,
                              void* d_out, int out_size)
{
    const float* X     = (const float*)d_in[0];
    const int*   edges = (const int*)d_in[1];     // int64 downcast to int32 by harness
    const float* W1    = (const float*)d_in[2];
    const float* b1    = (const float*)d_in[3];
    const float* Wfc   = (const float*)d_in[4];
    const float* bfc   = (const float*)d_in[5];
    float* out = (float*)d_out;

    const int n = in_sizes[0] / INDIM;
    const int E = in_sizes[1] / 2;
    const int* src = edges;
    const int* dst = edges + E;

    init_deg_kernel<<<(n + 255) / 256, 256>>>(n);
    deg_accum_kernel<<<(E + 255) / 256, 256>>>(dst, E, n);
    gemm1_mma_kernel<<<(n + 127) / 128, 256>>>(X, W1, n);
    scatter_kernel<<<(E * 16 + 255) / 256, 256>>>(src, dst, E, n);
    gemm2_kernel<<<(n + 23) / 24, dim3(10, 24)>>>(b1, Wfc, bfc, out, n);
}

// round 9
// speedup vs baseline: 1.0070x; 1.0070x over previous
#include <cuda_runtime.h>
#include <cuda_fp16.h>
#include <cstdint>

#define N_NODES 50000
#define HIDDEN  64
#define INDIM   512
#define OUTDIM  40

// Scratch (device globals)
__device__ __align__(16) __half2 g_hs_h[N_NODES * 32];    // fp16 dinv[i]*h[i]
__device__ __align__(16) float g_agg[N_NODES * HIDDEN];   // aggregated messages
__device__ __align__(16) float g_deg[N_NODES];
__device__ __align__(16) float g_dinv[N_NODES];

// ---------------------------------------------------------------------------
// Degree: deg[i] = 1 (self loop) + #edges with dst==i
// ---------------------------------------------------------------------------
__global__ void init_deg_kernel(int n) {
    int i = blockIdx.x * blockDim.x + threadIdx.x;
    if (i < n) g_deg[i] = 1.0f;
}

__global__ void deg_accum_kernel(const int* __restrict__ dst, int E, int n) {
    int e = blockIdx.x * blockDim.x + threadIdx.x;
    if (e < E) {
        int d = dst[e];
        if ((unsigned)d < (unsigned)n) atomicAdd(&g_deg[d], 1.0f);
    }
}

// ---------------------------------------------------------------------------
// GEMM1 (tensor cores, tf32): h[n,64] = X[n,512] @ W1[512,64]
// Fused epilogue: d = rsqrt(deg[row]); hs_h = fp16(d*h); agg = d*(d*h).
// ---------------------------------------------------------------------------
__device__ __forceinline__ uint32_t f2tf32(float f) {
    uint32_t r;
    asm("cvt.rna.tf32.f32 %0, %1;" : "=r"(r) : "f"(f));
    return r;
}

#define XS_STRIDE 36
#define WS_STRIDE 72

__global__ __launch_bounds__(256) void gemm1_mma_kernel(
    const float* __restrict__ X, const float* __restrict__ W, int n)
{
    __shared__ uint32_t Xs[128 * XS_STRIDE];
    __shared__ uint32_t Ws[32 * WS_STRIDE];

    const int tid  = threadIdx.x;
    const int lane = tid & 31;
    const int wid  = tid >> 5;
    const int gid  = lane >> 2;
    const int tig  = lane & 3;
    const int wrow = wid * 16;
    const int row0 = blockIdx.x * 128;

    float acc[8][4] = {};

    for (int k0 = 0; k0 < INDIM; k0 += 32) {
        #pragma unroll
        for (int t = 0; t < 4; t++) {
            int s = t * 256 + tid;
            int r = s >> 3, q = s & 7;
            int rr = row0 + r; if (rr >= n) rr = n - 1;
            float4 v = *(const float4*)(X + (size_t)rr * INDIM + k0 + q * 4);
            uint4 u = make_uint4(f2tf32(v.x), f2tf32(v.y), f2tf32(v.z), f2tf32(v.w));
            *(uint4*)(Xs + r * XS_STRIDE + q * 4) = u;
        }
        #pragma unroll
        for (int t = 0; t < 2; t++) {
            int s = t * 256 + tid;
            int kk = s >> 4, q = s & 15;
            float4 v = *(const float4*)(W + (size_t)(k0 + kk) * HIDDEN + q * 4);
            uint4 u = make_uint4(f2tf32(v.x), f2tf32(v.y), f2tf32(v.z), f2tf32(v.w));
            *(uint4*)(Ws + kk * WS_STRIDE + q * 4) = u;
        }
        __syncthreads();

        #pragma unroll
        for (int kk = 0; kk < 32; kk += 8) {
            uint32_t a0 = Xs[(wrow + gid) * XS_STRIDE + kk + tig];
            uint32_t a1 = Xs[(wrow + gid + 8) * XS_STRIDE + kk + tig];
            uint32_t a2 = Xs[(wrow + gid) * XS_STRIDE + kk + tig + 4];
            uint32_t a3 = Xs[(wrow + gid + 8) * XS_STRIDE + kk + tig + 4];
            #pragma unroll
            for (int nb = 0; nb < 8; nb++) {
                uint32_t b0 = Ws[(kk + tig) * WS_STRIDE + nb * 8 + gid];
                uint32_t b1 = Ws[(kk + tig + 4) * WS_STRIDE + nb * 8 + gid];
                asm volatile(
                    "mma.sync.aligned.m16n8k8.row.col.f32.tf32.tf32.f32 "
                    "{%0,%1,%2,%3}, {%4,%5,%6,%7}, {%8,%9}, {%0,%1,%2,%3};"
                    : "+f"(acc[nb][0]), "+f"(acc[nb][1]),
                      "+f"(acc[nb][2]), "+f"(acc[nb][3])
                    : "r"(a0), "r"(a1), "r"(a2), "r"(a3), "r"(b0), "r"(b1));
            }
        }
        __syncthreads();
    }

    // Fused epilogue
    const int rA = row0 + wrow + gid;
    const int rB = rA + 8;
    float dA = (rA < n) ? rsqrtf(g_deg[rA]) : 0.f;
    float dB = (rB < n) ? rsqrtf(g_deg[rB]) : 0.f;
    if (tig == 0) {
        if (rA < n) g_dinv[rA] = dA;
        if (rB < n) g_dinv[rB] = dB;
    }
    #pragma unroll
    for (int nb = 0; nb < 8; nb++) {
        int col = nb * 8 + 2 * tig;          // even column pair
        if (rA < n) {
            float h0 = dA * acc[nb][0], h1 = dA * acc[nb][1];
            g_hs_h[rA * 32 + (col >> 1)] = __floats2half2_rn(h0, h1);
            *(float2*)(g_agg + (size_t)rA * HIDDEN + col) =
                make_float2(dA * h0, dA * h1);
        }
        if (rB < n) {
            float h2 = dB * acc[nb][2], h3 = dB * acc[nb][3];
            g_hs_h[rB * 32 + (col >> 1)] = __floats2half2_rn(h2, h3);
            *(float2*)(g_agg + (size_t)rB * HIDDEN + col) =
                make_float2(dB * h2, dB * h3);
        }
    }
}

// ---------------------------------------------------------------------------
// Edge scatter: agg[dst,:] += dinv[dst] * hs[src,:]  (hs gathered in fp16)
// 16 threads per edge; uint2 (4 halves) gather, one v4 f32 L2 reduction each.
// ---------------------------------------------------------------------------
__device__ __forceinline__ void red_add_v4(float* addr, float4 v) {
    asm volatile("red.global.add.v4.f32 [%0], {%1, %2, %3, %4};"
                 :: "l"(__cvta_generic_to_global(addr)),
                    "f"(v.x), "f"(v.y), "f"(v.z), "f"(v.w)
                 : "memory");
}

__global__ __launch_bounds__(256) void scatter_kernel(
    const int* __restrict__ src, const int* __restrict__ dst, int E, int n)
{
    int idx = blockIdx.x * blockDim.x + threadIdx.x;
    if (idx >= E * 16) return;
    int e = idx >> 4, q = idx & 15;
    int s = __ldg(src + e);
    int d = __ldg(dst + e);
    if ((unsigned)s >= (unsigned)n || (unsigned)d >= (unsigned)n) return;
    float coef = g_dinv[d];

    uint2 raw = __ldg((const uint2*)g_hs_h + s * 16 + q);
    __half2 p0 = *(__half2*)&raw.x;
    __half2 p1 = *(__half2*)&raw.y;
    float2 f0 = __half22float2(p0);
    float2 f1 = __half22float2(p1);
    float4 v = make_float4(coef * f0.x, coef * f0.y, coef * f1.x, coef * f1.y);
    red_add_v4(g_agg + (size_t)d * HIDDEN + q * 4, v);
}

// ---------------------------------------------------------------------------
// GEMM2: out[n,40] = relu(agg + b1) @ Wfc^T + bfc
// ---------------------------------------------------------------------------
__global__ __launch_bounds__(240) void gemm2_kernel(
    const float* __restrict__ b1, const float* __restrict__ Wfc,
    const float* __restrict__ bfc, float* __restrict__ out, int n)
{
    __shared__ float hs[24 * 68];
    __shared__ float Wt[64 * 40];
    __shared__ float bfs[40];

    const int tx = threadIdx.x;     // 0..9
    const int ty = threadIdx.y;     // 0..23
    const int tid = ty * 10 + tx;

    for (int idx = tid; idx < 64 * 40; idx += 240) {
        int o = idx % 40, j = idx / 40;
        Wt[j * 40 + o] = Wfc[o * 64 + j];
    }
    if (tid < 40) bfs[tid] = bfc[tid];

    const int row0 = blockIdx.x * 24;
    for (int idx = tid; idx < 24 * 16; idx += 240) {
        int r = idx >> 4, q = idx & 15;
        int grow = row0 + r;
        float4 v = make_float4(0.f, 0.f, 0.f, 0.f);
        if (grow < n) {
            v = ((const float4*)g_agg)[grow * 16 + q];
            float4 bb = ((const float4*)b1)[q];
            v.x = fmaxf(v.x + bb.x, 0.f);
            v.y = fmaxf(v.y + bb.y, 0.f);
            v.z = fmaxf(v.z + bb.z, 0.f);
            v.w = fmaxf(v.w + bb.w, 0.f);
        }
        *(float4*)(hs + r * 68 + q * 4) = v;
    }
    __syncthreads();

    float4 acc = make_float4(0.f, 0.f, 0.f, 0.f);
    #pragma unroll
    for (int j = 0; j < 64; j++) {
        float h = hs[ty * 68 + j];
        float4 w = *(const float4*)(Wt + j * 40 + tx * 4);
        acc.x += h * w.x;
        acc.y += h * w.y;
        acc.z += h * w.z;
        acc.w += h * w.w;
    }

    int grow = row0 + ty;
    if (grow < n) {
        float4 bb = *(const float4*)(bfs + tx * 4);
        acc.x += bb.x; acc.y += bb.y; acc.z += bb.z; acc.w += bb.w;
        *(float4*)(out + (size_t)grow * OUTDIM + tx * 4) = acc;
    }
}

// ---------------------------------------------------------------------------
extern "C" void kernel_launch(void* const* d_in, const int* in_sizes, int n_in,
                              void* d_out, int out_size)
{
    const float* X     = (const float*)d_in[0];
    const int*   edges = (const int*)d_in[1];     // int64 downcast to int32 by harness
    const float* W1    = (const float*)d_in[2];
    const float* b1    = (const float*)d_in[3];
    const float* Wfc   = (const float*)d_in[4];
    const float* bfc   = (const float*)d_in[5];
    float* out = (float*)d_out;

    const int n = in_sizes[0] / INDIM;
    const int E = in_sizes[1] / 2;
    const int* src = edges;
    const int* dst = edges + E;

    init_deg_kernel<<<(n + 255) / 256, 256>>>(n);
    deg_accum_kernel<<<(E + 255) / 256, 256>>>(dst, E, n);
    gemm1_mma_kernel<<<(n + 127) / 128, 256>>>(X, W1, n);
    scatter_kernel<<<(E * 16 + 255) / 256, 256>>>(src, dst, E, n);
    gemm2_kernel<<<(n + 23) / 24, dim3(10, 24)>>>(b1, Wfc, bfc, out, n);
}

// round 10
// speedup vs baseline: 1.1087x; 1.1010x over previous
#include <cuda_runtime.h>
#include <cstdint>

#define N_NODES 50000
#define HIDDEN  64
#define INDIM   512
#define OUTDIM  40

// Scratch (device globals)
__device__ __align__(16) float g_hs[N_NODES * HIDDEN];    // dinv[i] * h[i]
__device__ __align__(16) float g_agg[N_NODES * HIDDEN];   // aggregated messages
__device__ __align__(16) float g_deg[N_NODES];
__device__ __align__(16) float g_dinv[N_NODES];

// ---------------------------------------------------------------------------
// Degree: deg[i] = 1 (self loop) + #edges with dst==i
// ---------------------------------------------------------------------------
__global__ void init_deg_kernel(int n) {
    int i = blockIdx.x * blockDim.x + threadIdx.x;
    if (i < n) g_deg[i] = 1.0f;
}

__global__ void deg_accum_kernel(const int* __restrict__ dst, int E, int n) {
    int e = blockIdx.x * blockDim.x + threadIdx.x;
    if (e < E) {
        int d = dst[e];
        if ((unsigned)d < (unsigned)n) atomicAdd(&g_deg[d], 1.0f);
    }
}

// ---------------------------------------------------------------------------
// GEMM1 (tensor cores, tf32): h[n,64] = X[n,512] @ W1[512,64]
// Fused epilogue: d = rsqrt(deg[row]); hs = d*h; agg = d*hs; dinv[row] = d.
// ---------------------------------------------------------------------------
__device__ __forceinline__ uint32_t f2tf32(float f) {
    uint32_t r;
    asm("cvt.rna.tf32.f32 %0, %1;" : "=r"(r) : "f"(f));
    return r;
}

#define XS_STRIDE 36
#define WS_STRIDE 72

__global__ __launch_bounds__(256) void gemm1_mma_kernel(
    const float* __restrict__ X, const float* __restrict__ W, int n)
{
    __shared__ uint32_t Xs[128 * XS_STRIDE];
    __shared__ uint32_t Ws[32 * WS_STRIDE];

    const int tid  = threadIdx.x;
    const int lane = tid & 31;
    const int wid  = tid >> 5;
    const int gid  = lane >> 2;
    const int tig  = lane & 3;
    const int wrow = wid * 16;
    const int row0 = blockIdx.x * 128;

    float acc[8][4] = {};

    for (int k0 = 0; k0 < INDIM; k0 += 32) {
        #pragma unroll
        for (int t = 0; t < 4; t++) {
            int s = t * 256 + tid;
            int r = s >> 3, q = s & 7;
            int rr = row0 + r; if (rr >= n) rr = n - 1;
            float4 v = *(const float4*)(X + (size_t)rr * INDIM + k0 + q * 4);
            uint4 u = make_uint4(f2tf32(v.x), f2tf32(v.y), f2tf32(v.z), f2tf32(v.w));
            *(uint4*)(Xs + r * XS_STRIDE + q * 4) = u;
        }
        #pragma unroll
        for (int t = 0; t < 2; t++) {
            int s = t * 256 + tid;
            int kk = s >> 4, q = s & 15;
            float4 v = *(const float4*)(W + (size_t)(k0 + kk) * HIDDEN + q * 4);
            uint4 u = make_uint4(f2tf32(v.x), f2tf32(v.y), f2tf32(v.z), f2tf32(v.w));
            *(uint4*)(Ws + kk * WS_STRIDE + q * 4) = u;
        }
        __syncthreads();

        #pragma unroll
        for (int kk = 0; kk < 32; kk += 8) {
            uint32_t a0 = Xs[(wrow + gid) * XS_STRIDE + kk + tig];
            uint32_t a1 = Xs[(wrow + gid + 8) * XS_STRIDE + kk + tig];
            uint32_t a2 = Xs[(wrow + gid) * XS_STRIDE + kk + tig + 4];
            uint32_t a3 = Xs[(wrow + gid + 8) * XS_STRIDE + kk + tig + 4];
            #pragma unroll
            for (int nb = 0; nb < 8; nb++) {
                uint32_t b0 = Ws[(kk + tig) * WS_STRIDE + nb * 8 + gid];
                uint32_t b1 = Ws[(kk + tig + 4) * WS_STRIDE + nb * 8 + gid];
                asm volatile(
                    "mma.sync.aligned.m16n8k8.row.col.f32.tf32.tf32.f32 "
                    "{%0,%1,%2,%3}, {%4,%5,%6,%7}, {%8,%9}, {%0,%1,%2,%3};"
                    : "+f"(acc[nb][0]), "+f"(acc[nb][1]),
                      "+f"(acc[nb][2]), "+f"(acc[nb][3])
                    : "r"(a0), "r"(a1), "r"(a2), "r"(a3), "r"(b0), "r"(b1));
            }
        }
        __syncthreads();
    }

    // Fused epilogue
    const int rA = row0 + wrow + gid;
    const int rB = rA + 8;
    float dA = (rA < n) ? rsqrtf(g_deg[rA]) : 0.f;
    float dB = (rB < n) ? rsqrtf(g_deg[rB]) : 0.f;
    if (tig == 0) {
        if (rA < n) g_dinv[rA] = dA;
        if (rB < n) g_dinv[rB] = dB;
    }
    #pragma unroll
    for (int nb = 0; nb < 8; nb++) {
        int col = nb * 8 + 2 * tig;
        if (rA < n) {
            float h0 = dA * acc[nb][0], h1 = dA * acc[nb][1];
            *(float2*)(g_hs  + (size_t)rA * HIDDEN + col) = make_float2(h0, h1);
            *(float2*)(g_agg + (size_t)rA * HIDDEN + col) =
                make_float2(dA * h0, dA * h1);
        }
        if (rB < n) {
            float h2 = dB * acc[nb][2], h3 = dB * acc[nb][3];
            *(float2*)(g_hs  + (size_t)rB * HIDDEN + col) = make_float2(h2, h3);
            *(float2*)(g_agg + (size_t)rB * HIDDEN + col) =
                make_float2(dB * h2, dB * h3);
        }
    }
}

// ---------------------------------------------------------------------------
// Edge scatter: agg[dst,:] += dinv[dst] * hs[src,:]
// 8 threads per edge, 2 float4 lanes each (q, q+8) for 2x MLP.
// ---------------------------------------------------------------------------
__device__ __forceinline__ void red_add_v4(float* addr, float4 v) {
    asm volatile("red.global.add.v4.f32 [%0], {%1, %2, %3, %4};"
                 :: "l"(__cvta_generic_to_global(addr)),
                    "f"(v.x), "f"(v.y), "f"(v.z), "f"(v.w)
                 : "memory");
}

__global__ __launch_bounds__(256) void scatter_kernel(
    const int* __restrict__ src, const int* __restrict__ dst, int E, int n)
{
    int idx = blockIdx.x * blockDim.x + threadIdx.x;
    if (idx >= E * 8) return;
    int e = idx >> 3, q = idx & 7;
    int s = __ldg(src + e);
    int d = __ldg(dst + e);
    if ((unsigned)s >= (unsigned)n || (unsigned)d >= (unsigned)n) return;
    float coef = g_dinv[d];

    // Two independent gathers (lanes q and q+8) -> 2x MLP
    float4 v0 = __ldg((const float4*)g_hs + s * 16 + q);
    float4 v1 = __ldg((const float4*)g_hs + s * 16 + q + 8);
    v0.x *= coef; v0.y *= coef; v0.z *= coef; v0.w *= coef;
    v1.x *= coef; v1.y *= coef; v1.z *= coef; v1.w *= coef;
    float* base = g_agg + (size_t)d * HIDDEN;
    red_add_v4(base + q * 4, v0);
    red_add_v4(base + (q + 8) * 4, v1);
}

// ---------------------------------------------------------------------------
// GEMM2: out[n,40] = relu(agg + b1) @ Wfc^T + bfc
// ---------------------------------------------------------------------------
__global__ __launch_bounds__(240) void gemm2_kernel(
    const float* __restrict__ b1, const float* __restrict__ Wfc,
    const float* __restrict__ bfc, float* __restrict__ out, int n)
{
    __shared__ float hs[24 * 68];
    __shared__ float Wt[64 * 40];
    __shared__ float bfs[40];

    const int tx = threadIdx.x;     // 0..9
    const int ty = threadIdx.y;     // 0..23
    const int tid = ty * 10 + tx;

    for (int idx = tid; idx < 64 * 40; idx += 240) {
        int o = idx % 40, j = idx / 40;
        Wt[j * 40 + o] = Wfc[o * 64 + j];
    }
    if (tid < 40) bfs[tid] = bfc[tid];

    const int row0 = blockIdx.x * 24;
    for (int idx = tid; idx < 24 * 16; idx += 240) {
        int r = idx >> 4, q = idx & 15;
        int grow = row0 + r;
        float4 v = make_float4(0.f, 0.f, 0.f, 0.f);
        if (grow < n) {
            v = ((const float4*)g_agg)[grow * 16 + q];
            float4 bb = ((const float4*)b1)[q];
            v.x = fmaxf(v.x + bb.x, 0.f);
            v.y = fmaxf(v.y + bb.y, 0.f);
            v.z = fmaxf(v.z + bb.z, 0.f);
            v.w = fmaxf(v.w + bb.w, 0.f);
        }
        *(float4*)(hs + r * 68 + q * 4) = v;
    }
    __syncthreads();

    float4 acc = make_float4(0.f, 0.f, 0.f, 0.f);
    #pragma unroll
    for (int j = 0; j < 64; j++) {
        float h = hs[ty * 68 + j];
        float4 w = *(const float4*)(Wt + j * 40 + tx * 4);
        acc.x += h * w.x;
        acc.y += h * w.y;
        acc.z += h * w.z;
        acc.w += h * w.w;
    }

    int grow = row0 + ty;
    if (grow < n) {
        float4 bb = *(const float4*)(bfs + tx * 4);
        acc.x += bb.x; acc.y += bb.y; acc.z += bb.z; acc.w += bb.w;
        *(float4*)(out + (size_t)grow * OUTDIM + tx * 4) = acc;
    }
}

// ---------------------------------------------------------------------------
extern "C" void kernel_launch(void* const* d_in, const int* in_sizes, int n_in,
                              void* d_out, int out_size)
{
    const float* X     = (const float*)d_in[0];
    const int*   edges = (const int*)d_in[1];     // int64 downcast to int32 by harness
    const float* W1    = (const float*)d_in[2];
    const float* b1    = (const float*)d_in[3];
    const float* Wfc   = (const float*)d_in[4];
    const float* bfc   = (const float*)d_in[5];
    float* out = (float*)d_out;

    const int n = in_sizes[0] / INDIM;
    const int E = in_sizes[1] / 2;
    const int* src = edges;
    const int* dst = edges + E;

    init_deg_kernel<<<(n + 255) / 256, 256>>>(n);
    deg_accum_kernel<<<(E + 255) / 256, 256>>>(dst, E, n);
    gemm1_mma_kernel<<<(n + 127) / 128, 256>>>(X, W1, n);
    scatter_kernel<<<(E * 8 + 255) / 256, 256>>>(src, dst, E, n);
    gemm2_kernel<<<(n + 23) / 24, dim3(10, 24)>>>(b1, Wfc, bfc, out, n);
}